// round 1
// baseline (speedup 1.0000x reference)
#include <cuda_runtime.h>
#include <cstdint>
#include <cstddef>

// Problem constants
#define Bsz 8
#define Cc  32
#define Oo  64
#define Hh  64
#define Ww  64
#define Kk  9

constexpr int SEG  = Ww * Kk;       // 576 floats: contiguous weight run for one (o,c,h)
constexpr int TILE = 16 * SEG;      // 9216 floats: 16 o-segments staged per c
constexpr int SMEM_BYTES = 2 * TILE * 4;  // double buffer = 73728 B

__device__ __forceinline__ void cp16(float* dst_smem, const float* src) {
    uint32_t s = (uint32_t)__cvta_generic_to_shared(dst_smem);
    asm volatile("cp.async.cg.shared.global [%0], [%1], 16;" :: "r"(s), "l"(src));
}

__global__ void __launch_bounds__(256, 2)
lc2d_kernel(const float* __restrict__ x,
            const float* __restrict__ wt,
            float* __restrict__ out)
{
    extern __shared__ float smem[];

    const int tx = threadIdx.x;
    const int w  = tx & 63;          // spatial column
    const int oq = tx >> 6;          // 0..3 : o-quad within block
    const int h  = blockIdx.x;       // spatial row
    const int ob = blockIdx.y * 16;  // block o base
    const int o0 = ob + oq * 4;      // this thread's first o

    const bool rup = (h > 0);
    const bool rdn = (h < Hh - 1);
    const bool cl  = (w > 0);
    const bool cr  = (w < Ww - 1);

    float acc[4][8];
    #pragma unroll
    for (int oo = 0; oo < 4; oo++)
        #pragma unroll
        for (int b = 0; b < 8; b++)
            acc[oo][b] = 0.f;

    // ---- stage weights for channel c into smem buffer `buf` (coalesced 16B cp.async) ----
    // weight region for (o in [ob,ob+16), c, h): 16 segments of 576 contiguous floats,
    // each segment base is 2304B-aligned. 2304 float4 total / 256 threads = 9 each.
    auto stage = [&](int c, int buf) {
        float* sb = smem + buf * TILE;
        #pragma unroll
        for (int i = 0; i < 9; i++) {
            int idx = tx + i * 256;           // float4 index 0..2303
            int seg = idx / 144;              // 144 float4 per segment
            int pos = idx - seg * 144;
            const float* g = wt + ((size_t)((ob + seg) * Cc + c) * Hh + h) * SEG + pos * 4;
            cp16(sb + seg * SEG + pos * 4, g);
        }
        asm volatile("cp.async.commit_group;");
    };

    stage(0, 0);  // prologue

    for (int c = 0; c < Cc; c++) {
        const int buf = c & 1;
        if (c + 1 < Cc) {
            stage(c + 1, buf ^ 1);
            asm volatile("cp.async.wait_group 1;");
        } else {
            asm volatile("cp.async.wait_group 0;");
        }
        __syncthreads();  // staged data visible to all threads

        // Weights for this thread's 4 o's: conflict-free scalar LDS (stride 9, gcd(9,32)=1)
        const float* sb = smem + buf * TILE;
        float wr[4][9];
        #pragma unroll
        for (int oo = 0; oo < 4; oo++) {
            const float* sp = sb + (oq * 4 + oo) * SEG + w * Kk;
            #pragma unroll
            for (int k = 0; k < 9; k++)
                wr[oo][k] = sp[k];
        }

        #pragma unroll
        for (int b = 0; b < Bsz; b++) {
            const float* xb = x + ((size_t)(b * Cc + c) * Hh + h) * Ww + w;
            float xv[9];
            xv[0] = (rup && cl) ? xb[-Ww - 1] : 0.f;
            xv[1] = rup         ? xb[-Ww    ] : 0.f;
            xv[2] = (rup && cr) ? xb[-Ww + 1] : 0.f;
            xv[3] = cl          ? xb[-1     ] : 0.f;
            xv[4] =               xb[0];
            xv[5] = cr          ? xb[ 1     ] : 0.f;
            xv[6] = (rdn && cl) ? xb[ Ww - 1] : 0.f;
            xv[7] = rdn         ? xb[ Ww    ] : 0.f;
            xv[8] = (rdn && cr) ? xb[ Ww + 1] : 0.f;

            #pragma unroll
            for (int oo = 0; oo < 4; oo++)
                #pragma unroll
                for (int k = 0; k < 9; k++)
                    acc[oo][b] = fmaf(wr[oo][k], xv[k], acc[oo][b]);
        }
        __syncthreads();  // protect buffer (buf^1 is overwritten next iteration)
    }

    // Coalesced output writes (consecutive w per warp)
    #pragma unroll
    for (int b = 0; b < Bsz; b++)
        #pragma unroll
        for (int oo = 0; oo < 4; oo++)
            out[((size_t)(b * Oo + o0 + oo) * Hh + h) * Ww + w] = acc[oo][b];
}

extern "C" void kernel_launch(void* const* d_in, const int* in_sizes, int n_in,
                              void* d_out, int out_size)
{
    const float* x  = (const float*)d_in[0];
    const float* wt = (const float*)d_in[1];
    float* out      = (float*)d_out;

    cudaFuncSetAttribute(lc2d_kernel,
                         cudaFuncAttributeMaxDynamicSharedMemorySize, SMEM_BYTES);

    dim3 grid(Hh, Oo / 16);   // 64 x 4 = 256 blocks
    lc2d_kernel<<<grid, 256, SMEM_BYTES>>>(x, wt, out);
}

// round 2
// speedup vs baseline: 1.6429x; 1.6429x over previous
#include <cuda_runtime.h>
#include <cstdint>
#include <cstddef>

#define Bsz 8
#define Cc  32
#define Oo  64
#define Hh  64
#define Ww  64
#define Kk  9

constexpr int OTILE = 8;                 // o's per block
constexpr int SEG   = Ww * Kk;           // 576 floats per (o,c,h)
constexpr int WTILE = OTILE * SEG;       // 4608 floats staged per c
constexpr int XCOL  = 66;                // padded columns (halo)
constexpr int XROW  = 3;
constexpr int XTILE = Bsz * XROW * XCOL; // 1584 floats per c
constexpr int SMEM_FLOATS = 2 * WTILE + 2 * XTILE;
constexpr int SMEM_BYTES  = SMEM_FLOATS * 4;   // 49536 B -> 4 CTAs/SM

__device__ __forceinline__ void cp16(float* dst_smem, const float* src) {
    uint32_t s = (uint32_t)__cvta_generic_to_shared(dst_smem);
    asm volatile("cp.async.cg.shared.global [%0], [%1], 16;" :: "r"(s), "l"(src));
}

__global__ void __launch_bounds__(256, 4)
lc2d_kernel(const float* __restrict__ x,
            const float* __restrict__ wt,
            float* __restrict__ out)
{
    extern __shared__ float smem[];
    float* wsm = smem;                    // [2][WTILE]
    float* xsm = smem + 2 * WTILE;        // [2][XTILE]

    const int tx = threadIdx.x;
    const int w  = tx & 63;
    const int oq = tx >> 6;               // 0..3
    const int h  = blockIdx.x;
    const int ob = blockIdx.y * OTILE;
    const int o0 = ob + oq * 2;           // this thread's 2 o's

    float acc[2][Bsz];
    #pragma unroll
    for (int oo = 0; oo < 2; oo++)
        #pragma unroll
        for (int b = 0; b < Bsz; b++)
            acc[oo][b] = 0.f;

    // ---- stage weights for channel c into buffer `buf` (coalesced 16B cp.async) ----
    auto stage_w = [&](int c, int buf) {
        float* sb = wsm + buf * WTILE;
        #pragma unroll
        for (int i = 0; i < 5; i++) {
            int idx = tx + i * 256;                 // float4 index, need < 1152
            if (idx < (WTILE / 4)) {
                int seg = idx / 144;                // 144 float4 per segment
                int pos = idx - seg * 144;
                const float* g = wt + ((size_t)((ob + seg) * Cc + c) * Hh + h) * SEG + pos * 4;
                cp16(sb + seg * SEG + pos * 4, g);
            }
        }
        asm volatile("cp.async.commit_group;");
    };

    // ---- stage zero-padded x halo tile for channel c: [b][3 rows][66 cols] ----
    auto stage_x = [&](int c, int buf) {
        float* sb = xsm + buf * XTILE;
        #pragma unroll
        for (int i = 0; i < 7; i++) {
            int idx = tx + i * 256;
            if (idx < XTILE) {
                int b   = idx / (XROW * XCOL);
                int rem = idx - b * (XROW * XCOL);
                int r   = rem / XCOL;
                int col = rem - r * XCOL;
                int grow = h - 1 + r;
                int gcol = col - 1;
                float v = 0.f;
                if (grow >= 0 && grow < Hh && gcol >= 0 && gcol < Ww)
                    v = x[((size_t)(b * Cc + c) * Hh + grow) * Ww + gcol];
                sb[idx] = v;
            }
        }
    };

    // prologue: stage c=0
    stage_w(0, 0);
    stage_x(0, 0);

    for (int c = 0; c < Cc; c++) {
        const int cur = c & 1;
        asm volatile("cp.async.wait_group 0;");
        __syncthreads();   // weights+x for c visible to all; prev buffers free

        if (c + 1 < Cc) {
            stage_w(c + 1, cur ^ 1);
            stage_x(c + 1, cur ^ 1);
        }

        // weights for this thread's 2 o's (conflict-free: stride 9 vs 32 banks)
        const float* wb = wsm + cur * WTILE;
        float wr[2][Kk];
        #pragma unroll
        for (int oo = 0; oo < 2; oo++) {
            const float* sp = wb + (oq * 2 + oo) * SEG + w * Kk;
            #pragma unroll
            for (int k = 0; k < Kk; k++)
                wr[oo][k] = sp[k];
        }

        const float* xb = xsm + cur * XTILE;
        #pragma unroll
        for (int b = 0; b < Bsz; b++) {
            const float* xp = xb + b * (XROW * XCOL) + w;   // col w => padded index w (= w-1+1)
            float xv[9];
            #pragma unroll
            for (int r = 0; r < 3; r++) {
                xv[r * 3 + 0] = xp[r * XCOL + 0];
                xv[r * 3 + 1] = xp[r * XCOL + 1];
                xv[r * 3 + 2] = xp[r * XCOL + 2];
            }
            #pragma unroll
            for (int oo = 0; oo < 2; oo++)
                #pragma unroll
                for (int k = 0; k < Kk; k++)
                    acc[oo][b] = fmaf(wr[oo][k], xv[k], acc[oo][b]);
        }
        __syncthreads();   // all reads of `cur` done before it is overwritten
    }

    #pragma unroll
    for (int b = 0; b < Bsz; b++)
        #pragma unroll
        for (int oo = 0; oo < 2; oo++)
            out[((size_t)(b * Oo + o0 + oo) * Hh + h) * Ww + w] = acc[oo][b];
}

extern "C" void kernel_launch(void* const* d_in, const int* in_sizes, int n_in,
                              void* d_out, int out_size)
{
    const float* x  = (const float*)d_in[0];
    const float* wt = (const float*)d_in[1];
    float* out      = (float*)d_out;

    cudaFuncSetAttribute(lc2d_kernel,
                         cudaFuncAttributeMaxDynamicSharedMemorySize, SMEM_BYTES);

    dim3 grid(Hh, Oo / OTILE);   // 64 x 8 = 512 blocks
    lc2d_kernel<<<grid, 256, SMEM_BYTES>>>(x, wt, out);
}

// round 3
// speedup vs baseline: 2.6141x; 1.5912x over previous
#include <cuda_runtime.h>
#include <cstdint>
#include <cstddef>

#define Bsz 8
#define Cc  32
#define Oo  64
#define Hh  64
#define Ww  64
#define Kk  9

constexpr int OTILE = 8;                  // o's per block
constexpr int SEG   = Ww * Kk;            // 576 floats per (o,c,h)
constexpr int WTILE = OTILE * SEG;        // 4608 floats per c
constexpr int XROWS = 3;
constexpr int XCOLP = 72;                 // padded row: [3]=col -1, [4..67]=cols 0..63, [68]=col 64
constexpr int XTILE = Bsz * XROWS * XCOLP;// 1728 floats per c
constexpr int SMEM_BYTES = (2 * WTILE + 2 * XTILE) * 4;  // 50688 B -> 4 CTAs/SM

// cp.async with explicit src-size: sz=16 copies, sz=0 zero-fills (for OOB rows)
__device__ __forceinline__ void cp16(float* dst_smem, const float* src, int sz) {
    uint32_t a = (uint32_t)__cvta_generic_to_shared(dst_smem);
    asm volatile("cp.async.cg.shared.global [%0], [%1], 16, %2;"
                 :: "r"(a), "l"(src), "r"(sz));
}

__global__ void __launch_bounds__(128, 4)
lc2d_kernel(const float* __restrict__ x,
            const float* __restrict__ wt,
            float* __restrict__ out)
{
    extern __shared__ float smem[];
    float* wsm = smem;                    // [2][WTILE]
    float* xsm = smem + 2 * WTILE;        // [2][XTILE]

    const int tx = threadIdx.x;           // 128 threads
    const int w  = tx & 63;
    const int oq = tx >> 6;               // 0..1
    const int h  = blockIdx.x;
    const int ob = blockIdx.y * OTILE;
    const int o0 = ob + oq * 4;           // this thread's 4 o's

    // ---- one-time: zero the halo columns (offsets 3 and 68 of every row, both buffers)
    if (tx < 96) {
        int bufsel = tx / 48;
        int t      = tx - bufsel * 48;
        int b      = t / 6;
        int q      = t - b * 6;
        int r      = q >> 1;
        int side   = q & 1;
        xsm[bufsel * XTILE + (b * XROWS + r) * XCOLP + (side ? 68 : 3)] = 0.f;
    }

    float acc[4][Bsz];
    #pragma unroll
    for (int oo = 0; oo < 4; oo++)
        #pragma unroll
        for (int b = 0; b < Bsz; b++)
            acc[oo][b] = 0.f;

    // ---- stage weights for channel c: 1152 float4 across 128 threads = 9 each (exact)
    auto stage_w = [&](int c, int buf) {
        float* sb = wsm + buf * WTILE;
        #pragma unroll
        for (int i = 0; i < 9; i++) {
            int idx = tx + i * 128;            // < 1152
            int seg = idx / 144;               // 144 float4 per o-segment
            int pos = idx - seg * 144;
            const float* g = wt + ((size_t)((ob + seg) * Cc + c) * Hh + h) * SEG + pos * 4;
            cp16(sb + seg * SEG + pos * 4, g, 16);
        }
    };

    // ---- stage x halo tile for channel c: 8b x 3r x 16 float4 = 384 cp16, 3 per thread
    auto stage_x = [&](int c, int buf) {
        float* sb = xsm + buf * XTILE;
        #pragma unroll
        for (int i = 0; i < 3; i++) {
            int idx = tx + i * 128;            // < 384
            int b   = idx / 48;
            int rem = idx - b * 48;
            int r   = rem >> 4;
            int j   = rem & 15;
            int grow = h - 1 + r;
            int sz   = (grow >= 0 && grow < Hh) ? 16 : 0;
            int gr   = grow < 0 ? 0 : (grow > Hh - 1 ? Hh - 1 : grow);
            const float* src = x + ((size_t)(b * Cc + c) * Hh + gr) * Ww + j * 4;
            cp16(sb + (b * XROWS + r) * XCOLP + 4 + j * 4, src, sz);
        }
    };

    // prologue
    stage_w(0, 0);
    stage_x(0, 0);
    asm volatile("cp.async.commit_group;");

    for (int c = 0; c < Cc; c++) {
        const int cur = c & 1;
        asm volatile("cp.async.wait_group 0;");
        __syncthreads();                       // data for c visible; prev buffer free

        if (c + 1 < Cc) {
            stage_w(c + 1, cur ^ 1);
            stage_x(c + 1, cur ^ 1);
            asm volatile("cp.async.commit_group;");
        }

        // weights for 4 o's: conflict-free scalar LDS (lane stride 9 vs 32 banks)
        const float* wb = wsm + cur * WTILE;
        float wr[4][Kk];
        #pragma unroll
        for (int oo = 0; oo < 4; oo++) {
            const float* sp = wb + (oq * 4 + oo) * SEG + w * Kk;
            #pragma unroll
            for (int k = 0; k < Kk; k++)
                wr[oo][k] = sp[k];
        }

        const float* xb = xsm + cur * XTILE;
        #pragma unroll
        for (int b = 0; b < Bsz; b++) {
            const float* xp = xb + b * (XROWS * XCOLP) + 3 + w;  // window start (col w-1)
            float xv[9];
            #pragma unroll
            for (int r = 0; r < 3; r++) {
                xv[r * 3 + 0] = xp[r * XCOLP + 0];
                xv[r * 3 + 1] = xp[r * XCOLP + 1];
                xv[r * 3 + 2] = xp[r * XCOLP + 2];
            }
            #pragma unroll
            for (int oo = 0; oo < 4; oo++)
                #pragma unroll
                for (int k = 0; k < Kk; k++)
                    acc[oo][b] = fmaf(wr[oo][k], xv[k], acc[oo][b]);
        }
        __syncthreads();                       // reads of `cur` done before overwrite
    }

    #pragma unroll
    for (int b = 0; b < Bsz; b++)
        #pragma unroll
        for (int oo = 0; oo < 4; oo++)
            out[((size_t)(b * Oo + o0 + oo) * Hh + h) * Ww + w] = acc[oo][b];
}

extern "C" void kernel_launch(void* const* d_in, const int* in_sizes, int n_in,
                              void* d_out, int out_size)
{
    const float* x  = (const float*)d_in[0];
    const float* wt = (const float*)d_in[1];
    float* out      = (float*)d_out;

    cudaFuncSetAttribute(lc2d_kernel,
                         cudaFuncAttributeMaxDynamicSharedMemorySize, SMEM_BYTES);

    dim3 grid(Hh, Oo / OTILE);   // 64 x 8 = 512 blocks of 128 threads
    lc2d_kernel<<<grid, 128, SMEM_BYTES>>>(x, wt, out);
}

// round 4
// speedup vs baseline: 2.6156x; 1.0006x over previous
#include <cuda_runtime.h>
#include <cstdint>
#include <cstddef>

#define Bsz 8
#define Cc  32
#define Oo  64
#define Hh  64
#define Ww  64
#define Kk  9

constexpr int OTILE = 8;                  // o's per block
constexpr int SEG   = Ww * Kk;            // 576 floats per (o,c,h)
constexpr int WTILE = OTILE * SEG;        // 4608 floats per c
constexpr int XROWS = 3;
constexpr int XCOLP = 72;                 // [3]=col -1, [4..67]=cols 0..63, [68]=col 64
constexpr int XTILE = Bsz * XROWS * XCOLP;// 1728 floats per c
constexpr int SMEM_BYTES = (2 * WTILE + 2 * XTILE) * 4;  // 50688 B -> 4 CTAs/SM
constexpr int WC_STRIDE = Hh * SEG;       // weight float-offset advance per channel
constexpr int XC_STRIDE = Hh * Ww;        // x float-offset advance per channel

__device__ __forceinline__ void cp16(float* dst_smem, const float* src, int sz) {
    uint32_t a = (uint32_t)__cvta_generic_to_shared(dst_smem);
    asm volatile("cp.async.cg.shared.global [%0], [%1], 16, %2;"
                 :: "r"(a), "l"(src), "r"(sz));
}

__global__ void __launch_bounds__(128, 4)
lc2d_kernel(const float* __restrict__ x,
            const float* __restrict__ wt,
            float* __restrict__ out)
{
    extern __shared__ float smem[];
    float* wsm = smem;                    // [2][WTILE]
    float* xsm = smem + 2 * WTILE;        // [2][XTILE]

    const int tx = threadIdx.x;           // 128 threads
    const int w  = tx & 63;
    const int oq = tx >> 6;               // 0..1
    const int h  = blockIdx.x;
    const int ob = blockIdx.y * OTILE;
    const int o0 = ob + oq * 4;

    // one-time halo zeros (cols 3 and 68 of every row, both buffers)
    if (tx < 96) {
        int bufsel = tx / 48;
        int t      = tx - bufsel * 48;
        int b      = t / 6;
        int q      = t - b * 6;
        int r      = q >> 1;
        int side   = q & 1;
        xsm[bufsel * XTILE + (b * XROWS + r) * XCOLP + (side ? 68 : 3)] = 0.f;
    }

    // ---- per-thread loop-invariant staging descriptors ----
    // weights: 9 cp16/thread; idx = tx + i*128; seg = idx/144; pos = idx - seg*144
    int  wgo[9];   // marching gmem float offsets (start at c=0)
    int  wso[9];   // smem float offsets within a buffer
    #pragma unroll
    for (int i = 0; i < 9; i++) {
        int idx = tx + i * 128;
        int seg = idx / 144;
        int pos = idx - seg * 144;
        wgo[i] = (((ob + seg) * Cc) * Hh + h) * SEG + pos * 4;
        wso[i] = seg * SEG + pos * 4;
    }
    // x: 3 cp16/thread; idx = tx + i*128 (<384)
    int  xgo[3];   // marching gmem float offsets (c=0)
    int  xso[3];
    int  xsz[3];
    #pragma unroll
    for (int i = 0; i < 3; i++) {
        int idx = tx + i * 128;
        int b   = idx / 48;
        int rem = idx - b * 48;
        int r   = rem >> 4;
        int j   = rem & 15;
        int grow = h - 1 + r;
        xsz[i]  = (grow >= 0 && grow < Hh) ? 16 : 0;
        int gr  = grow < 0 ? 0 : (grow > Hh - 1 ? Hh - 1 : grow);
        xgo[i]  = ((b * Cc) * Hh + gr) * Ww + j * 4;
        xso[i]  = (b * XROWS + r) * XCOLP + 4 + j * 4;
    }

    float acc[4][Bsz];
    #pragma unroll
    for (int oo = 0; oo < 4; oo++)
        #pragma unroll
        for (int b = 0; b < Bsz; b++)
            acc[oo][b] = 0.f;

    auto stage = [&](int buf) {   // stages current wgo/xgo, then advances them
        float* wb = wsm + buf * WTILE;
        #pragma unroll
        for (int i = 0; i < 9; i++) {
            cp16(wb + wso[i], wt + wgo[i], 16);
            wgo[i] += WC_STRIDE;
        }
        float* xb = xsm + buf * XTILE;
        #pragma unroll
        for (int i = 0; i < 3; i++) {
            cp16(xb + xso[i], x + xgo[i], xsz[i]);
            xgo[i] += XC_STRIDE;
        }
        asm volatile("cp.async.commit_group;");
    };

    stage(0);   // prologue: c=0

    #pragma unroll 2
    for (int c = 0; c < Cc; c++) {
        const int cur = c & 1;
        asm volatile("cp.async.wait_group 0;");
        __syncthreads();   // data for c visible; ALSO proves all warps done reading buf cur^1

        if (c + 1 < Cc)
            stage(cur ^ 1);

        // weights for 4 o's: conflict-free scalar LDS (lane stride 9 vs 32 banks)
        const float* wb = wsm + cur * WTILE + oq * 4 * SEG + w * Kk;
        float wr[4][Kk];
        #pragma unroll
        for (int oo = 0; oo < 4; oo++) {
            #pragma unroll
            for (int k = 0; k < Kk; k++)
                wr[oo][k] = wb[oo * SEG + k];
        }

        const float* xp = xsm + cur * XTILE + 3 + w;
        #pragma unroll
        for (int b = 0; b < Bsz; b++) {
            float xv[9];
            #pragma unroll
            for (int r = 0; r < 3; r++) {
                xv[r * 3 + 0] = xp[r * XCOLP + 0];
                xv[r * 3 + 1] = xp[r * XCOLP + 1];
                xv[r * 3 + 2] = xp[r * XCOLP + 2];
            }
            #pragma unroll
            for (int oo = 0; oo < 4; oo++)
                #pragma unroll
                for (int k = 0; k < Kk; k++)
                    acc[oo][b] = fmaf(wr[oo][k], xv[k], acc[oo][b]);
            xp += XROWS * XCOLP;
        }
        // no end-of-loop barrier: top-of-loop sync of iteration c+1 protects buffers
    }

    float* op = out + ((size_t)o0 * Hh + h) * Ww + w;
    #pragma unroll
    for (int b = 0; b < Bsz; b++)
        #pragma unroll
        for (int oo = 0; oo < 4; oo++)
            op[(size_t)(b * Oo + oo) * (Hh * Ww)] = acc[oo][b];
}

extern "C" void kernel_launch(void* const* d_in, const int* in_sizes, int n_in,
                              void* d_out, int out_size)
{
    const float* x  = (const float*)d_in[0];
    const float* wt = (const float*)d_in[1];
    float* out      = (float*)d_out;

    cudaFuncSetAttribute(lc2d_kernel,
                         cudaFuncAttributeMaxDynamicSharedMemorySize, SMEM_BYTES);

    dim3 grid(Hh, Oo / OTILE);   // 64 x 8 = 512 blocks of 128 threads
    lc2d_kernel<<<grid, 128, SMEM_BYTES>>>(x, wt, out);
}